// round 3
// baseline (speedup 1.0000x reference)
#include <cuda_runtime.h>
#include <cuda_bf16.h>

// ht[b,d] = sum_{s=start}^{start+x-1} hidden[b,s,d]
// start = sum(mask[B-1, :]) - x   (JAX x64-disabled: mask & x are int32)
//
// Grid: B * (D4/16) blocks (512 for B=32, D=1024).
// Block: 256 threads = 16 float4-cols x 16 s-groups.
// Each thread sums 4 rows (stride 16) into 4 independent accumulators so all
// 4 LDG.128s are in flight simultaneously (MLP=4/thread, ~8MB chip-wide).

__global__ void __launch_bounds__(256)
srsmlp_window_sum_kernel(const float* __restrict__ hidden,
                         const int* __restrict__ mask,
                         const int* __restrict__ xptr,
                         float* __restrict__ out,
                         int B, int S, int D4, int chunks /* D4/16 */)
{
    const int tid = threadIdx.x;
    const int col = tid & 15;         // float4 column within 16-wide chunk
    const int sg  = tid >> 4;         // s-group 0..15
    const int b     = blockIdx.x / chunks;
    const int chunk = blockIdx.x - b * chunks;

    // ---- 1) block-local reduction of mask[B-1, :] -> session length ----
    __shared__ int s_len;
    if (tid == 0) s_len = 0;
    __syncthreads();

    const int x = *xptr;              // independent load, issued early
    {
        const int* mrow = mask + (long long)(B - 1) * S;
        const int  S4   = S >> 2;
        const int4* mrow4 = reinterpret_cast<const int4*>(mrow);
        int acc = 0;
        for (int i = tid; i < S4; i += 256) {        // 2 batched int4 loads
            int4 v = mrow4[i];
            acc += v.x + v.y + v.z + v.w;
        }
        for (int i = (S4 << 2) + tid; i < S; i += 256)
            acc += mrow[i];
        #pragma unroll
        for (int off = 16; off > 0; off >>= 1)
            acc += __shfl_down_sync(0xFFFFFFFFu, acc, off);
        if ((tid & 31) == 0)
            atomicAdd(&s_len, acc);
    }
    __syncthreads();

    const int start = s_len - x;

    // ---- 2) windowed sum, 4 independent float4 accumulators ----
    const int d4 = (chunk << 4) + col;
    const float4* __restrict__ base =
        reinterpret_cast<const float4*>(hidden) +
        ((long long)b * S + start) * D4 + d4;

    float4 a0 = make_float4(0.f,0.f,0.f,0.f);
    float4 a1 = a0, a2 = a0, a3 = a0;

    int r = sg;
    for (; r + 48 < x; r += 64) {     // one iter for x=64: rows sg,+16,+32,+48
        float4 v0 = base[(long long)(r)      * D4];
        float4 v1 = base[(long long)(r + 16) * D4];
        float4 v2 = base[(long long)(r + 32) * D4];
        float4 v3 = base[(long long)(r + 48) * D4];
        a0.x += v0.x; a0.y += v0.y; a0.z += v0.z; a0.w += v0.w;
        a1.x += v1.x; a1.y += v1.y; a1.z += v1.z; a1.w += v1.w;
        a2.x += v2.x; a2.y += v2.y; a2.z += v2.z; a2.w += v2.w;
        a3.x += v3.x; a3.y += v3.y; a3.z += v3.z; a3.w += v3.w;
    }
    for (; r < x; r += 16) {          // tail for general x
        float4 v = base[(long long)r * D4];
        a0.x += v.x; a0.y += v.y; a0.z += v.z; a0.w += v.w;
    }
    a0.x += a1.x + a2.x + a3.x;
    a0.y += a1.y + a2.y + a3.y;
    a0.z += a1.z + a2.z + a3.z;
    a0.w += a1.w + a2.w + a3.w;

    // ---- 3) reduce 16 s-groups in shared memory ----
    __shared__ float4 red[16][16];    // 4 KB
    red[sg][col] = a0;
    __syncthreads();

    if (tid < 16) {                   // col = tid
        float4 t = red[0][tid];
        #pragma unroll
        for (int j = 1; j < 16; ++j) {
            float4 v = red[j][tid];
            t.x += v.x; t.y += v.y; t.z += v.z; t.w += v.w;
        }
        reinterpret_cast<float4*>(out)[(long long)b * D4 + d4] = t;
    }
}

extern "C" void kernel_launch(void* const* d_in, const int* in_sizes, int n_in,
                              void* d_out, int out_size)
{
    const float* hidden = (const float*)d_in[0];
    const int*   mask   = (const int*)d_in[1];
    const int*   xptr   = (const int*)d_in[2];
    float*       out    = (float*)d_out;

    const long long hidden_elems = in_sizes[0];
    const long long mask_elems   = in_sizes[1];

    const int D  = (int)(hidden_elems / mask_elems);  // 1024
    const int B  = out_size / D;                      // 32
    const int S  = (int)(mask_elems / B);             // 2048
    const int D4 = D >> 2;                            // 256
    const int chunks = D4 >> 4;                       // 16 cols of float4 per block

    dim3 grid(B * chunks);                            // 512 blocks
    srsmlp_window_sum_kernel<<<grid, 256>>>(hidden, mask, xptr, out,
                                            B, S, D4, chunks);
}